// round 10
// baseline (speedup 1.0000x reference)
#include <cuda_runtime.h>

// Fused transformer block. B=2048, T=128, DM=32, H=2, DK=16.
// CTA = 256 threads, 2 batches. Attention: thread (hb,h,u) -> rows (u,127-u), head h.
// Post-attention: 8-warp split — Wo by output half, FFN by hidden half (+smem reduction).
// Packed fma.rn.f32x2 throughout. grid = 1024.

typedef unsigned long long u64;

namespace {
constexpr int Bsz = 2048;
constexpr int T   = 128;
constexpr int DM  = 32;
constexpr int KVS = 36;   // K/V row stride (floats)
constexpr int AST = 66;   // interleaved row-buffer stride (floats): 64 data + 2 pad

// shared layout (floats)
constexpr int OFF_A  = 0;       // 4096: phase A = Wq|Wk|Wv (3072), phase B = W1 (4096)
constexpr int OFF_W2 = 4096;    // 4096
constexpr int OFF_WO = 8192;    // 1024
constexpr int OFF_B  = 9216;    // 320: bo[32] b1[128] b2[32] g1[32] be1[32] g2[32] be2[32]
constexpr int OFF_KV = 9536;    // 2 batches * (K 4608 + V 4608); later: attnF buffer
constexpr int OFF_P  = OFF_KV + 128 * AST;   // x2 buffer / (never overlapping attnF)
constexpr int SMEM_FLOATS = OFF_KV + 2 * 2 * T * KVS;   // 27968  (OFF_P+8448=26432 fits)
constexpr int SMEM_BYTES  = SMEM_FLOATS * 4;            // 111872 -> 2 CTAs/SM
}

// ---- packed f32x2 helpers ----
__device__ __forceinline__ void ffma2(u64& acc, u64 a, u64 b) {
    asm("fma.rn.f32x2 %0, %1, %2, %0;" : "+l"(acc) : "l"(a), "l"(b));
}
__device__ __forceinline__ void fadd2(u64& a, u64 b) {
    asm("add.rn.f32x2 %0, %0, %1;" : "+l"(a) : "l"(b));
}
__device__ __forceinline__ u64 bcast2(float x) {
    u64 r; unsigned xi = __float_as_uint(x);
    asm("mov.b64 %0, {%1, %1};" : "=l"(r) : "r"(xi));
    return r;
}
__device__ __forceinline__ u64 pk2(float lo, float hi) {
    u64 r; unsigned a = __float_as_uint(lo), b = __float_as_uint(hi);
    asm("mov.b64 %0, {%1, %2};" : "=l"(r) : "r"(a), "r"(b));
    return r;
}
__device__ __forceinline__ float2 unpk(u64 v) {
    unsigned lo, hi;
    asm("mov.b64 {%0, %1}, %2;" : "=r"(lo), "=r"(hi) : "l"(v));
    return make_float2(__uint_as_float(lo), __uint_as_float(hi));
}
__device__ __forceinline__ void split_bcast(u64 v, u64& m0, u64& m1) {
    unsigned lo, hi;
    asm("mov.b64 {%0, %1}, %2;" : "=r"(lo), "=r"(hi) : "l"(v));
    asm("mov.b64 %0, {%1, %1};" : "=l"(m0) : "r"(lo));
    asm("mov.b64 %0, {%1, %1};" : "=l"(m1) : "r"(hi));
}

__device__ __forceinline__ void ln_row(float* x, const float* g, const float* be) {
    float mu = 0.f;
    #pragma unroll
    for (int d = 0; d < DM; d++) mu += x[d];
    mu *= (1.f / DM);
    float var = 0.f;
    #pragma unroll
    for (int d = 0; d < DM; d++) { float c = x[d] - mu; var = fmaf(c, c, var); }
    var *= (1.f / DM);
    float r = rsqrtf(var + 1e-5f);
    #pragma unroll
    for (int d = 0; d < DM; d++) x[d] = (x[d] - mu) * r * g[d] + be[d];
}

// one-head projection for two rows: W is [32 d][16 j]
__device__ __forceinline__ void proj_h(const float* __restrict__ W,
                                       const float* __restrict__ xa,
                                       const float* __restrict__ xb,
                                       u64* oa, u64* ob) {
    #pragma unroll 8
    for (int d = 0; d < 32; d++) {
        u64 ma = bcast2(xa[d]), mb = bcast2(xb[d]);
        const ulonglong2* wp = (const ulonglong2*)(W + d * 16);
        #pragma unroll
        for (int t = 0; t < 4; t++) {
            ulonglong2 wv = wp[t];
            ffma2(oa[2*t],   ma, wv.x); ffma2(oa[2*t+1],   ma, wv.y);
            ffma2(ob[2*t],   mb, wv.x); ffma2(ob[2*t+1],   mb, wv.y);
        }
    }
}

__device__ __forceinline__ float dot8r(const u64* q2, const ulonglong2* kv) {
    u64 s0 = 0, s1 = 0;
    #pragma unroll
    for (int t = 0; t < 4; t++) { ffma2(s0, q2[2*t], kv[t].x); ffma2(s1, q2[2*t+1], kv[t].y); }
    float2 a = unpk(s0), b = unpk(s1);
    return (a.x + a.y) + (b.x + b.y);
}

__global__ void __launch_bounds__(256, 2) block_kernel(
    const float* __restrict__ gx,
    const float* __restrict__ gWq, const float* __restrict__ gWk, const float* __restrict__ gWv,
    const float* __restrict__ gWo, const float* __restrict__ gbo,
    const float* __restrict__ gW1, const float* __restrict__ gb1,
    const float* __restrict__ gW2, const float* __restrict__ gb2,
    const float* __restrict__ gg1, const float* __restrict__ gbe1,
    const float* __restrict__ gg2, const float* __restrict__ gbe2,
    float* __restrict__ gout)
{
    extern __shared__ float sm[];
    float* sA    = sm + OFF_A;      // QKV then W1
    float* sW2   = sm + OFF_W2;
    float* sWo   = sm + OFF_WO;
    float* sbo   = sm + OFF_B;
    float* sb1   = sm + OFF_B + 32;
    float* sb2   = sm + OFF_B + 160;
    float* sg1   = sm + OFF_B + 192;
    float* sbe1  = sm + OFF_B + 224;
    float* sg2   = sm + OFF_B + 256;
    float* sbe2  = sm + OFF_B + 288;
    float* attnF = sm + OFF_KV;     // post phases: interleaved attn/x1/partial rows

    const int tid = threadIdx.x;
    const int hb  = tid >> 7;             // attention: local batch 0/1
    const int t7  = tid & 127;
    const int h   = t7 >> 6;              // head 0/1
    const int u   = t7 & 63;
    const int ra  = u;
    const int rb  = 127 - u;
    const long gb = (long)blockIdx.x * 2 + hb;

    float* sK = sm + OFF_KV + hb * (2 * T * KVS);
    float* sV = sK + T * KVS;

    // ---- phase A: cooperative weight loads ----
    {
        float4*       dq = (float4*)sA;
        const float4* s;
        s = (const float4*)gWq; for (int i = tid; i < 256;  i += 256) dq[i]       = s[i];
        s = (const float4*)gWk; for (int i = tid; i < 256;  i += 256) dq[256 + i] = s[i];
        s = (const float4*)gWv; for (int i = tid; i < 256;  i += 256) dq[512 + i] = s[i];
        float4* d2 = (float4*)sW2; s = (const float4*)gW2; for (int i = tid; i < 1024; i += 256) d2[i] = s[i];
        float4* d3 = (float4*)sWo; s = (const float4*)gWo; for (int i = tid; i < 256;  i += 256) d3[i] = s[i];
        if (tid < 32) {
            sbo[tid]  = gbo[tid];  sb2[tid]  = gb2[tid];
            sg1[tid]  = gg1[tid];  sbe1[tid] = gbe1[tid];
            sg2[tid]  = gg2[tid];  sbe2[tid] = gbe2[tid];
        }
        if (tid < 128) sb1[tid] = gb1[tid];
    }
    __syncthreads();

    // ---- x rows + LN1 ----
    float xa[DM], xb[DM];
    {
        const float4* pa = (const float4*)(gx + (gb * T + ra) * DM);
        const float4* pb = (const float4*)(gx + (gb * T + rb) * DM);
        #pragma unroll
        for (int i = 0; i < 8; i++) {
            float4 v = pa[i]; xa[4*i] = v.x; xa[4*i+1] = v.y; xa[4*i+2] = v.z; xa[4*i+3] = v.w;
            float4 w = pb[i]; xb[4*i] = w.x; xb[4*i+1] = w.y; xb[4*i+2] = w.z; xb[4*i+3] = w.w;
        }
        ln_row(xa, sg1, sbe1);
        ln_row(xb, sg1, sbe1);
    }

    // ---- head-h projections: k, v to smem; q kept live ----
    {
        u64 k2a[8], k2b[8];
        #pragma unroll
        for (int p = 0; p < 8; p++) { k2a[p] = 0; k2b[p] = 0; }
        proj_h(sA + 1024 + h * 512, xa, xb, k2a, k2b);
        u64* krA = (u64*)(sK + ra * KVS + h * 16);
        u64* krB = (u64*)(sK + rb * KVS + h * 16);
        #pragma unroll
        for (int p = 0; p < 8; p++) { krA[p] = k2a[p]; krB[p] = k2b[p]; }
    }
    {
        u64 v2a[8], v2b[8];
        #pragma unroll
        for (int p = 0; p < 8; p++) { v2a[p] = 0; v2b[p] = 0; }
        proj_h(sA + 2048 + h * 512, xa, xb, v2a, v2b);
        u64* vrA = (u64*)(sV + ra * KVS + h * 16);
        u64* vrB = (u64*)(sV + rb * KVS + h * 16);
        #pragma unroll
        for (int p = 0; p < 8; p++) { vrA[p] = v2a[p]; vrB[p] = v2b[p]; }
    }
    u64 qa2[8], qb2[8];
    #pragma unroll
    for (int p = 0; p < 8; p++) { qa2[p] = 0; qb2[p] = 0; }
    proj_h(sA + h * 512, xa, xb, qa2, qb2);

    __syncthreads();   // K/V visible; QKV weights dead

    // stage W1 into region A (overlaps attention)
    {
        const float4* s = (const float4*)gW1;
        float4*       d = (float4*)sA;
        #pragma unroll
        for (int i = tid; i < 1024; i += 256) d[i] = s[i];
    }

    // ---- attention: rows (u,127-u), head h; two warp-uniform segments ----
    u64 aa2[8], ab2[8];
    #pragma unroll
    for (int p = 0; p < 8; p++) { aa2[p] = 0; ab2[p] = 0; }
    float la = 0.f, lb = 0.f;

    const int ub     = u & 32;
    const int wa_max = ub + 31;
    const int wb_max = 127 - ub;
    const float* kh = sK + h * 16;
    const float* vh = sV + h * 16;

    for (int s = 0; s <= wa_max; s++) {
        const ulonglong2* kp = (const ulonglong2*)(kh + s * KVS);
        ulonglong2 kv[4];
        #pragma unroll
        for (int q = 0; q < 4; q++) kv[q] = kp[q];
        float da = dot8r(qa2, kv);
        float db = dot8r(qb2, kv);
        float pa = (s <= ra) ? __expf(da) : 0.f;
        float pb = __expf(db);
        la += pa; lb += pb;

        const ulonglong2* vp = (const ulonglong2*)(vh + s * KVS);
        ulonglong2 vv[4];
        #pragma unroll
        for (int q = 0; q < 4; q++) vv[q] = vp[q];
        u64 Pa = bcast2(pa), Pb = bcast2(pb);
        #pragma unroll
        for (int q = 0; q < 4; q++) {
            ffma2(aa2[2*q],   Pa, vv[q].x); ffma2(aa2[2*q+1],   Pa, vv[q].y);
            ffma2(ab2[2*q],   Pb, vv[q].x); ffma2(ab2[2*q+1],   Pb, vv[q].y);
        }
    }
    for (int s = wa_max + 1; s <= wb_max; s++) {
        const ulonglong2* kp = (const ulonglong2*)(kh + s * KVS);
        ulonglong2 kv[4];
        #pragma unroll
        for (int q = 0; q < 4; q++) kv[q] = kp[q];
        float db = dot8r(qb2, kv);
        float pb = (s <= rb) ? __expf(db) : 0.f;
        lb += pb;

        const ulonglong2* vp = (const ulonglong2*)(vh + s * KVS);
        u64 Pb = bcast2(pb);
        #pragma unroll
        for (int q = 0; q < 4; q++) {
            ulonglong2 vv = vp[q];
            ffma2(ab2[2*q], Pb, vv.x); ffma2(ab2[2*q+1], Pb, vv.y);
        }
    }

    __syncthreads();   // all K/V reads done; region becomes interleaved attn buffer

    // ---- store normalized attn, batch-interleaved: attnF[r*AST + 2*j + hb] ----
    {
        float ia = 1.f / la, ib = 1.f / lb;
        float* pA = attnF + ra * AST + hb;
        float* pB = attnF + rb * AST + hb;
        #pragma unroll
        for (int p = 0; p < 8; p++) {
            int j0 = 16 * h + 2 * p;
            float2 f = unpk(aa2[p]);
            pA[2*j0]       = f.x * ia;
            pA[2*(j0+1)]   = f.y * ia;
            float2 g = unpk(ab2[p]);
            pB[2*j0]       = g.x * ib;
            pB[2*(j0+1)]   = g.y * ib;
        }
    }
    __syncthreads();

    // ==== post-attention: all 256 threads. jh = output/hidden half, t = row ====
    const int jh = tid >> 7;      // 0/1
    const int t  = tid & 127;
    const long gB0 = (long)blockIdx.x * 2;
    const long gB1 = gB0 + 1;
    float* myrow = attnF + t * AST;          // attn row -> x1 row -> partial row
    float* prow  = sm + OFF_P + t * AST;     // x2 row

    // Wo half accumulators init with residual LN1(x)[half] + bo
    u64 oA[8], oB[8];
    {
        float xA[DM], xB[DM];
        const float4* p0 = (const float4*)(gx + (gB0 * T + t) * DM);
        const float4* p1 = (const float4*)(gx + (gB1 * T + t) * DM);
        #pragma unroll
        for (int i = 0; i < 8; i++) {
            float4 v = p0[i]; xA[4*i] = v.x; xA[4*i+1] = v.y; xA[4*i+2] = v.z; xA[4*i+3] = v.w;
            float4 w = p1[i]; xB[4*i] = w.x; xB[4*i+1] = w.y; xB[4*i+2] = w.z; xB[4*i+3] = w.w;
        }
        ln_row(xA, sg1, sbe1);
        ln_row(xB, sg1, sbe1);
        #pragma unroll
        for (int p = 0; p < 8; p++) {
            const int c = 16 * jh + 2 * p;
            oA[p] = pk2(xA[c] + sbo[c], xA[c+1] + sbo[c+1]);
            oB[p] = pk2(xB[c] + sbo[c], xB[c+1] + sbo[c+1]);
        }
    }

    // attn @ Wo (half of outputs, both batches share each Wo load)
    #pragma unroll 4
    for (int e = 0; e < 32; e++) {
        u64 ap = *(const u64*)(myrow + 2 * e);
        u64 m0, m1; split_bcast(ap, m0, m1);
        const ulonglong2* wp = (const ulonglong2*)(sWo + e * 32 + jh * 16);
        #pragma unroll
        for (int q = 0; q < 4; q++) {
            ulonglong2 wv = wp[q];
            ffma2(oA[2*q], m0, wv.x); ffma2(oA[2*q+1], m0, wv.y);
            ffma2(oB[2*q], m1, wv.x); ffma2(oB[2*q+1], m1, wv.y);
        }
    }
    __syncthreads();   // all attn reads of myrow done before x1 overwrite

    // write x1 half into attnF (interleaved (b0,b1) per col)
    #pragma unroll
    for (int p = 0; p < 8; p++) {
        const int c = 16 * jh + 2 * p;
        float2 f = unpk(oA[p]);
        float2 g = unpk(oB[p]);
        *(u64*)(myrow + 2 * c)       = pk2(f.x, g.x);
        *(u64*)(myrow + 2 * (c + 1)) = pk2(f.y, g.y);
    }
    __syncthreads();   // both halves of x1 visible

    // LN2 (duplicated on both jh threads of a row); x2 -> prow; FFN accum init
    u64 r2a[16], r2b[16];
    {
        float x1A[DM], x1B[DM];
        #pragma unroll
        for (int d = 0; d < DM; d++) {
            float2 f = unpk(*(const u64*)(myrow + 2 * d));
            x1A[d] = f.x; x1B[d] = f.y;
        }
        ln_row(x1A, sg2, sbe2);
        ln_row(x1B, sg2, sbe2);
        // both jh threads write identical values; each reads only its own row later
        #pragma unroll
        for (int d = 0; d < DM; d++) *(u64*)(prow + 2 * d) = pk2(x1A[d], x1B[d]);
        if (jh == 0) {
            #pragma unroll
            for (int p = 0; p < 16; p++) {
                r2a[p] = pk2(x1A[2*p] + sb2[2*p], x1A[2*p+1] + sb2[2*p+1]);
                r2b[p] = pk2(x1B[2*p] + sb2[2*p], x1B[2*p+1] + sb2[2*p+1]);
            }
        } else {
            #pragma unroll
            for (int p = 0; p < 16; p++) { r2a[p] = 0; r2b[p] = 0; }
        }
    }

    // ---- FFN: hidden half [64*jh, 64*jh+64), full-width partial outputs ----
    #pragma unroll 1
    for (int blk = 4 * jh; blk < 4 * jh + 4; blk++) {
        const float* w1p = sA + blk * 16;
        u64 h0[8], h1[8];
        #pragma unroll
        for (int p = 0; p < 8; p++) { h0[p] = 0; h1[p] = 0; }
        #pragma unroll 4
        for (int d = 0; d < 32; d++) {
            u64 xp = *(const u64*)(prow + 2 * d);
            u64 m0, m1; split_bcast(xp, m0, m1);
            const ulonglong2* wp = (const ulonglong2*)(w1p + d * 128);
            #pragma unroll
            for (int q = 0; q < 4; q++) {
                ulonglong2 wv = wp[q];
                ffma2(h0[2*q],   m0, wv.x); ffma2(h0[2*q+1],   m0, wv.y);
                ffma2(h1[2*q],   m1, wv.x); ffma2(h1[2*q+1],   m1, wv.y);
            }
        }
        #pragma unroll
        for (int p = 0; p < 8; p++) {
            const int j = blk * 16 + 2 * p;
            float2 f0 = unpk(h0[p]);
            float2 f1 = unpk(h1[p]);
            float A0 = fmaxf(f0.x + sb1[j],     0.f);
            float A1 = fmaxf(f0.y + sb1[j + 1], 0.f);
            float B0 = fmaxf(f1.x + sb1[j],     0.f);
            float B1 = fmaxf(f1.y + sb1[j + 1], 0.f);
            {
                u64 Pa = bcast2(A0), Pb = bcast2(B0);
                const ulonglong2* w2 = (const ulonglong2*)(sW2 + j * 32);
                #pragma unroll
                for (int q = 0; q < 8; q++) {
                    ulonglong2 wv = w2[q];
                    ffma2(r2a[2*q], Pa, wv.x); ffma2(r2a[2*q+1], Pa, wv.y);
                    ffma2(r2b[2*q], Pb, wv.x); ffma2(r2b[2*q+1], Pb, wv.y);
                }
            }
            {
                u64 Pa = bcast2(A1), Pb = bcast2(B1);
                const ulonglong2* w2 = (const ulonglong2*)(sW2 + (j + 1) * 32);
                #pragma unroll
                for (int q = 0; q < 8; q++) {
                    ulonglong2 wv = w2[q];
                    ffma2(r2a[2*q], Pa, wv.x); ffma2(r2a[2*q+1], Pa, wv.y);
                    ffma2(r2b[2*q], Pb, wv.x); ffma2(r2b[2*q+1], Pb, wv.y);
                }
            }
        }
    }

    // jh=1: stash partials in attnF row (x1 values dead)
    if (jh == 1) {
        u64* pr = (u64*)myrow;
        #pragma unroll
        for (int p = 0; p < 16; p++) { pr[p] = r2a[p]; pr[16 + p] = r2b[p]; }
    }
    __syncthreads();

    // jh=0: reduce partner partials, store both batches' row t
    if (jh == 0) {
        const u64* pr = (const u64*)myrow;
        #pragma unroll
        for (int p = 0; p < 16; p++) { fadd2(r2a[p], pr[p]); fadd2(r2b[p], pr[16 + p]); }
        ulonglong2* o0 = (ulonglong2*)(gout + (gB0 * T + t) * DM);
        ulonglong2* o1 = (ulonglong2*)(gout + (gB1 * T + t) * DM);
        #pragma unroll
        for (int q = 0; q < 8; q++) {
            o0[q] = make_ulonglong2(r2a[2*q], r2a[2*q+1]);
            o1[q] = make_ulonglong2(r2b[2*q], r2b[2*q+1]);
        }
    }
}

extern "C" void kernel_launch(void* const* d_in, const int* in_sizes, int n_in,
                              void* d_out, int out_size)
{
    const float* x   = (const float*)d_in[0];
    const float* Wq  = (const float*)d_in[1];
    const float* Wk  = (const float*)d_in[2];
    const float* Wv  = (const float*)d_in[3];
    const float* Wo  = (const float*)d_in[4];
    const float* bo  = (const float*)d_in[5];
    const float* W1  = (const float*)d_in[6];
    const float* b1  = (const float*)d_in[7];
    const float* W2  = (const float*)d_in[8];
    const float* b2  = (const float*)d_in[9];
    const float* g1  = (const float*)d_in[10];
    const float* be1 = (const float*)d_in[11];
    const float* g2  = (const float*)d_in[12];
    const float* be2 = (const float*)d_in[13];
    float* out = (float*)d_out;

    cudaFuncSetAttribute(block_kernel, cudaFuncAttributeMaxDynamicSharedMemorySize, SMEM_BYTES);
    block_kernel<<<Bsz / 2, 256, SMEM_BYTES>>>(x, Wq, Wk, Wv, Wo, bo, W1, b1, W2, b2,
                                               g1, be1, g2, be2, out);
}

// round 11
// speedup vs baseline: 1.0257x; 1.0257x over previous
#include <cuda_runtime.h>

// Fused transformer block. B=2048, T=128, DM=32, H=2, DK=16.
// CTA = 256 threads, 2 batches. Attention: thread (hb,h,u) -> rows (u,127-u), head h,
// with K-row register double-buffering (software pipeline). Post-attention: threads
// 0..127 own row r for BOTH batches (cross-batch weight reuse). fma.rn.f32x2 throughout.

typedef unsigned long long u64;

namespace {
constexpr int Bsz = 2048;
constexpr int T   = 128;
constexpr int DM  = 32;
constexpr int KVS = 36;   // K/V row stride (floats)
constexpr int AST = 66;   // attn/x2 interleaved buffer row stride (floats)

constexpr int OFF_A  = 0;       // 4096: phase A = Wq|Wk|Wv (3072), phase B = W1 (4096)
constexpr int OFF_W2 = 4096;    // 4096
constexpr int OFF_WO = 8192;    // 1024
constexpr int OFF_B  = 9216;    // 320
constexpr int OFF_KV = 9536;    // 2 batches * (K 4608 + V 4608); attnF aliases later
constexpr int SMEM_FLOATS = OFF_KV + 2 * 2 * T * KVS;   // 27968
constexpr int SMEM_BYTES  = SMEM_FLOATS * 4;            // 111872 -> 2 CTAs/SM
}

__device__ __forceinline__ void ffma2(u64& acc, u64 a, u64 b) {
    asm("fma.rn.f32x2 %0, %1, %2, %0;" : "+l"(acc) : "l"(a), "l"(b));
}
__device__ __forceinline__ u64 bcast2(float x) {
    u64 r; unsigned xi = __float_as_uint(x);
    asm("mov.b64 %0, {%1, %1};" : "=l"(r) : "r"(xi));
    return r;
}
__device__ __forceinline__ u64 pk2(float lo, float hi) {
    u64 r; unsigned a = __float_as_uint(lo), b = __float_as_uint(hi);
    asm("mov.b64 %0, {%1, %2};" : "=l"(r) : "r"(a), "r"(b));
    return r;
}
__device__ __forceinline__ float2 unpk(u64 v) {
    unsigned lo, hi;
    asm("mov.b64 {%0, %1}, %2;" : "=r"(lo), "=r"(hi) : "l"(v));
    return make_float2(__uint_as_float(lo), __uint_as_float(hi));
}
__device__ __forceinline__ void split_bcast(u64 v, u64& m0, u64& m1) {
    unsigned lo, hi;
    asm("mov.b64 {%0, %1}, %2;" : "=r"(lo), "=r"(hi) : "l"(v));
    asm("mov.b64 %0, {%1, %1};" : "=l"(m0) : "r"(lo));
    asm("mov.b64 %0, {%1, %1};" : "=l"(m1) : "r"(hi));
}

__device__ __forceinline__ void ln_row(float* x, const float* g, const float* be) {
    float mu = 0.f;
    #pragma unroll
    for (int d = 0; d < DM; d++) mu += x[d];
    mu *= (1.f / DM);
    float var = 0.f;
    #pragma unroll
    for (int d = 0; d < DM; d++) { float c = x[d] - mu; var = fmaf(c, c, var); }
    var *= (1.f / DM);
    float r = rsqrtf(var + 1e-5f);
    #pragma unroll
    for (int d = 0; d < DM; d++) x[d] = (x[d] - mu) * r * g[d] + be[d];
}

__device__ __forceinline__ void proj_h(const float* __restrict__ W,
                                       const float* __restrict__ xa,
                                       const float* __restrict__ xb,
                                       u64* oa, u64* ob) {
    #pragma unroll 8
    for (int d = 0; d < 32; d++) {
        u64 ma = bcast2(xa[d]), mb = bcast2(xb[d]);
        const ulonglong2* wp = (const ulonglong2*)(W + d * 16);
        #pragma unroll
        for (int t = 0; t < 4; t++) {
            ulonglong2 wv = wp[t];
            ffma2(oa[2*t],   ma, wv.x); ffma2(oa[2*t+1],   ma, wv.y);
            ffma2(ob[2*t],   mb, wv.x); ffma2(ob[2*t+1],   mb, wv.y);
        }
    }
}

__device__ __forceinline__ float dot8r(const u64* q2, const ulonglong2* kv) {
    u64 s0 = 0, s1 = 0;
    #pragma unroll
    for (int t = 0; t < 4; t++) { ffma2(s0, q2[2*t], kv[t].x); ffma2(s1, q2[2*t+1], kv[t].y); }
    float2 a = unpk(s0), b = unpk(s1);
    return (a.x + a.y) + (b.x + b.y);
}

__global__ void __launch_bounds__(256, 2) block_kernel(
    const float* __restrict__ gx,
    const float* __restrict__ gWq, const float* __restrict__ gWk, const float* __restrict__ gWv,
    const float* __restrict__ gWo, const float* __restrict__ gbo,
    const float* __restrict__ gW1, const float* __restrict__ gb1,
    const float* __restrict__ gW2, const float* __restrict__ gb2,
    const float* __restrict__ gg1, const float* __restrict__ gbe1,
    const float* __restrict__ gg2, const float* __restrict__ gbe2,
    float* __restrict__ gout)
{
    extern __shared__ float sm[];
    float* sA    = sm + OFF_A;
    float* sW2   = sm + OFF_W2;
    float* sWo   = sm + OFF_WO;
    float* sbo   = sm + OFF_B;
    float* sb1   = sm + OFF_B + 32;
    float* sb2   = sm + OFF_B + 160;
    float* sg1   = sm + OFF_B + 192;
    float* sbe1  = sm + OFF_B + 224;
    float* sg2   = sm + OFF_B + 256;
    float* sbe2  = sm + OFF_B + 288;
    float* attnF = sm + OFF_KV;

    const int tid = threadIdx.x;
    const int hb  = tid >> 7;
    const int t7  = tid & 127;
    const int h   = t7 >> 6;
    const int u   = t7 & 63;
    const int ra  = u;
    const int rb  = 127 - u;
    const long gb = (long)blockIdx.x * 2 + hb;

    float* sK = sm + OFF_KV + hb * (2 * T * KVS);
    float* sV = sK + T * KVS;

    // ---- phase A: cooperative weight loads ----
    {
        float4*       dq = (float4*)sA;
        const float4* s;
        s = (const float4*)gWq; for (int i = tid; i < 256;  i += 256) dq[i]       = s[i];
        s = (const float4*)gWk; for (int i = tid; i < 256;  i += 256) dq[256 + i] = s[i];
        s = (const float4*)gWv; for (int i = tid; i < 256;  i += 256) dq[512 + i] = s[i];
        float4* d2 = (float4*)sW2; s = (const float4*)gW2; for (int i = tid; i < 1024; i += 256) d2[i] = s[i];
        float4* d3 = (float4*)sWo; s = (const float4*)gWo; for (int i = tid; i < 256;  i += 256) d3[i] = s[i];
        if (tid < 32) {
            sbo[tid]  = gbo[tid];  sb2[tid]  = gb2[tid];
            sg1[tid]  = gg1[tid];  sbe1[tid] = gbe1[tid];
            sg2[tid]  = gg2[tid];  sbe2[tid] = gbe2[tid];
        }
        if (tid < 128) sb1[tid] = gb1[tid];
    }
    __syncthreads();

    // ---- x rows + LN1 ----
    float xa[DM], xb[DM];
    {
        const float4* pa = (const float4*)(gx + (gb * T + ra) * DM);
        const float4* pb = (const float4*)(gx + (gb * T + rb) * DM);
        #pragma unroll
        for (int i = 0; i < 8; i++) {
            float4 v = pa[i]; xa[4*i] = v.x; xa[4*i+1] = v.y; xa[4*i+2] = v.z; xa[4*i+3] = v.w;
            float4 w = pb[i]; xb[4*i] = w.x; xb[4*i+1] = w.y; xb[4*i+2] = w.z; xb[4*i+3] = w.w;
        }
        ln_row(xa, sg1, sbe1);
        ln_row(xb, sg1, sbe1);
    }

    // ---- head-h projections: k, v to smem; q kept live ----
    {
        u64 k2a[8], k2b[8];
        #pragma unroll
        for (int p = 0; p < 8; p++) { k2a[p] = 0; k2b[p] = 0; }
        proj_h(sA + 1024 + h * 512, xa, xb, k2a, k2b);
        u64* krA = (u64*)(sK + ra * KVS + h * 16);
        u64* krB = (u64*)(sK + rb * KVS + h * 16);
        #pragma unroll
        for (int p = 0; p < 8; p++) { krA[p] = k2a[p]; krB[p] = k2b[p]; }
    }
    {
        u64 v2a[8], v2b[8];
        #pragma unroll
        for (int p = 0; p < 8; p++) { v2a[p] = 0; v2b[p] = 0; }
        proj_h(sA + 2048 + h * 512, xa, xb, v2a, v2b);
        u64* vrA = (u64*)(sV + ra * KVS + h * 16);
        u64* vrB = (u64*)(sV + rb * KVS + h * 16);
        #pragma unroll
        for (int p = 0; p < 8; p++) { vrA[p] = v2a[p]; vrB[p] = v2b[p]; }
    }
    u64 qa2[8], qb2[8];
    #pragma unroll
    for (int p = 0; p < 8; p++) { qa2[p] = 0; qb2[p] = 0; }
    proj_h(sA + h * 512, xa, xb, qa2, qb2);

    __syncthreads();   // K/V visible; QKV weights dead

    // stage W1 into region A (overlaps attention)
    {
        const float4* s = (const float4*)gW1;
        float4*       d = (float4*)sA;
        #pragma unroll
        for (int i = tid; i < 1024; i += 256) d[i] = s[i];
    }

    // ---- attention: rows (u,127-u), head h; K double-buffered in registers ----
    u64 aa2[8], ab2[8];
    #pragma unroll
    for (int p = 0; p < 8; p++) { aa2[p] = 0; ab2[p] = 0; }
    float la = 0.f, lb = 0.f;

    const int ub     = u & 32;
    const int wa_max = ub + 31;
    const int wb_max = 127 - ub;
    const float* kh = sK + h * 16;
    const float* vh = sV + h * 16;

    // segment 1: s = 0..wa_max (32 or 64 iters, even)
    {
        const float* kptr = kh;
        ulonglong2 kv[4];
        #pragma unroll
        for (int q = 0; q < 4; q++) kv[q] = ((const ulonglong2*)kptr)[q];
        const float* vptr = vh;

        #pragma unroll 2
        for (int s = 0; s <= wa_max; s++) {
            // prefetch next K row (row s+1 <= 64, always valid)
            const float* knp = kptr + KVS;
            ulonglong2 kn[4];
            #pragma unroll
            for (int q = 0; q < 4; q++) kn[q] = ((const ulonglong2*)knp)[q];

            // V row s (consumed late in the iteration)
            ulonglong2 vv[4];
            #pragma unroll
            for (int q = 0; q < 4; q++) vv[q] = ((const ulonglong2*)vptr)[q];

            float da = dot8r(qa2, kv);
            float db = dot8r(qb2, kv);
            float pa = (s <= ra) ? __expf(da) : 0.f;
            float pb = __expf(db);
            la += pa; lb += pb;

            u64 Pa = bcast2(pa), Pb = bcast2(pb);
            #pragma unroll
            for (int q = 0; q < 4; q++) {
                ffma2(aa2[2*q],   Pa, vv[q].x); ffma2(aa2[2*q+1],   Pa, vv[q].y);
                ffma2(ab2[2*q],   Pb, vv[q].x); ffma2(ab2[2*q+1],   Pb, vv[q].y);
            }
            #pragma unroll
            for (int q = 0; q < 4; q++) kv[q] = kn[q];
            kptr = knp;
            vptr += KVS;
        }
    }
    // segment 2: s = wa_max+1..wb_max (96 or 32 iters, even); row b only
    {
        const float* kptr = kh + (wa_max + 1) * KVS;
        ulonglong2 kv[4];
        #pragma unroll
        for (int q = 0; q < 4; q++) kv[q] = ((const ulonglong2*)kptr)[q];
        const float* vptr = vh + (wa_max + 1) * KVS;

        #pragma unroll 2
        for (int s = wa_max + 1; s <= wb_max; s++) {
            // prefetch next K row (row wb_max+1 <= 128 reads V row 0: in-bounds, never used)
            const float* knp = kptr + KVS;
            ulonglong2 kn[4];
            #pragma unroll
            for (int q = 0; q < 4; q++) kn[q] = ((const ulonglong2*)knp)[q];

            ulonglong2 vv[4];
            #pragma unroll
            for (int q = 0; q < 4; q++) vv[q] = ((const ulonglong2*)vptr)[q];

            float db = dot8r(qb2, kv);
            float pb = (s <= rb) ? __expf(db) : 0.f;
            lb += pb;

            u64 Pb = bcast2(pb);
            #pragma unroll
            for (int q = 0; q < 4; q++) {
                ffma2(ab2[2*q], Pb, vv[q].x); ffma2(ab2[2*q+1], Pb, vv[q].y);
            }
            #pragma unroll
            for (int q = 0; q < 4; q++) kv[q] = kn[q];
            kptr = knp;
            vptr += KVS;
        }
    }

    __syncthreads();   // all K/V reads done; region becomes interleaved attn buffer

    // ---- store normalized attn, batch-interleaved: attnF[r*AST + 2*j + hb] ----
    {
        float ia = 1.f / la, ib = 1.f / lb;
        float* pA = attnF + ra * AST + hb;
        float* pB = attnF + rb * AST + hb;
        #pragma unroll
        for (int p = 0; p < 8; p++) {
            int j0 = 16 * h + 2 * p;
            float2 f = unpk(aa2[p]);
            pA[2*j0]       = f.x * ia;
            pA[2*(j0+1)]   = f.y * ia;
            float2 g = unpk(ab2[p]);
            pB[2*j0]       = g.x * ib;
            pB[2*(j0+1)]   = g.y * ib;
        }
    }
    __syncthreads();

    // ==== post-attention: threads 0..127, row t for BOTH batches ====
    if (tid >= 128) return;
    const int t = tid;
    const long gB0 = (long)blockIdx.x * 2;
    const long gB1 = gB0 + 1;

    // Wo accumulators initialized with residual LN1(x) + bo
    u64 oA[16], oB[16];
    {
        float xA[DM], xB[DM];
        const float4* p0 = (const float4*)(gx + (gB0 * T + t) * DM);
        const float4* p1 = (const float4*)(gx + (gB1 * T + t) * DM);
        #pragma unroll
        for (int i = 0; i < 8; i++) {
            float4 v = p0[i]; xA[4*i] = v.x; xA[4*i+1] = v.y; xA[4*i+2] = v.z; xA[4*i+3] = v.w;
            float4 w = p1[i]; xB[4*i] = w.x; xB[4*i+1] = w.y; xB[4*i+2] = w.z; xB[4*i+3] = w.w;
        }
        ln_row(xA, sg1, sbe1);
        ln_row(xB, sg1, sbe1);
        #pragma unroll
        for (int p = 0; p < 16; p++) {
            oA[p] = pk2(xA[2*p] + sbo[2*p], xA[2*p+1] + sbo[2*p+1]);
            oB[p] = pk2(xB[2*p] + sbo[2*p], xB[2*p+1] + sbo[2*p+1]);
        }
    }

    // attn @ Wo, both batches share each Wo load
    const float* myrow = attnF + t * AST;
    #pragma unroll 4
    for (int e = 0; e < 32; e++) {
        u64 ap = *(const u64*)(myrow + 2 * e);
        u64 m0, m1; split_bcast(ap, m0, m1);
        const ulonglong2* wp = (const ulonglong2*)(sWo + e * 32);
        #pragma unroll
        for (int q = 0; q < 8; q++) {
            ulonglong2 wv = wp[q];
            ffma2(oA[2*q], m0, wv.x); ffma2(oA[2*q+1], m0, wv.y);
            ffma2(oB[2*q], m1, wv.x); ffma2(oB[2*q+1], m1, wv.y);
        }
    }

    // LN2, stash x2 pairs in smem (same row, in place), init FFN residual accumulators
    u64 r2a[16], r2b[16];
    {
        float x2A[DM], x2B[DM];
        #pragma unroll
        for (int p = 0; p < 16; p++) {
            float2 f = unpk(oA[p]); x2A[2*p] = f.x; x2A[2*p+1] = f.y;
            float2 g = unpk(oB[p]); x2B[2*p] = g.x; x2B[2*p+1] = g.y;
        }
        ln_row(x2A, sg2, sbe2);
        ln_row(x2B, sg2, sbe2);
        u64* xrow = (u64*)myrow;
        #pragma unroll
        for (int d = 0; d < 32; d++) xrow[d] = pk2(x2A[d], x2B[d]);
        #pragma unroll
        for (int p = 0; p < 16; p++) {
            r2a[p] = pk2(x2A[2*p] + sb2[2*p], x2A[2*p+1] + sb2[2*p+1]);
            r2b[p] = pk2(x2B[2*p] + sb2[2*p], x2B[2*p+1] + sb2[2*p+1]);
        }
    }

    // ---- FFN: hidden in blocks of 16; x2 pairs re-read from smem; weights shared 2 rows ----
    #pragma unroll 1
    for (int blk = 0; blk < 8; blk++) {
        const float* w1p = sA + blk * 16;
        u64 h0[8], h1[8];
        #pragma unroll
        for (int p = 0; p < 8; p++) { h0[p] = 0; h1[p] = 0; }
        #pragma unroll 4
        for (int d = 0; d < 32; d++) {
            u64 xp = *(const u64*)(myrow + 2 * d);
            u64 m0, m1; split_bcast(xp, m0, m1);
            const ulonglong2* wp = (const ulonglong2*)(w1p + d * 128);
            #pragma unroll
            for (int q = 0; q < 4; q++) {
                ulonglong2 wv = wp[q];
                ffma2(h0[2*q],   m0, wv.x); ffma2(h0[2*q+1],   m0, wv.y);
                ffma2(h1[2*q],   m1, wv.x); ffma2(h1[2*q+1],   m1, wv.y);
            }
        }
        #pragma unroll
        for (int p = 0; p < 8; p++) {
            const int j = blk * 16 + 2 * p;
            float2 f0 = unpk(h0[p]);
            float2 f1 = unpk(h1[p]);
            float A0 = fmaxf(f0.x + sb1[j],     0.f);
            float A1 = fmaxf(f0.y + sb1[j + 1], 0.f);
            float B0 = fmaxf(f1.x + sb1[j],     0.f);
            float B1 = fmaxf(f1.y + sb1[j + 1], 0.f);
            {
                u64 Pa = bcast2(A0), Pb = bcast2(B0);
                const ulonglong2* w2 = (const ulonglong2*)(sW2 + j * 32);
                #pragma unroll
                for (int q = 0; q < 8; q++) {
                    ulonglong2 wv = w2[q];
                    ffma2(r2a[2*q], Pa, wv.x); ffma2(r2a[2*q+1], Pa, wv.y);
                    ffma2(r2b[2*q], Pb, wv.x); ffma2(r2b[2*q+1], Pb, wv.y);
                }
            }
            {
                u64 Pa = bcast2(A1), Pb = bcast2(B1);
                const ulonglong2* w2 = (const ulonglong2*)(sW2 + (j + 1) * 32);
                #pragma unroll
                for (int q = 0; q < 8; q++) {
                    ulonglong2 wv = w2[q];
                    ffma2(r2a[2*q], Pa, wv.x); ffma2(r2a[2*q+1], Pa, wv.y);
                    ffma2(r2b[2*q], Pb, wv.x); ffma2(r2b[2*q+1], Pb, wv.y);
                }
            }
        }
    }

    // ---- store both batches' row t ----
    ulonglong2* o0 = (ulonglong2*)(gout + (gB0 * T + t) * DM);
    ulonglong2* o1 = (ulonglong2*)(gout + (gB1 * T + t) * DM);
    #pragma unroll
    for (int q = 0; q < 8; q++) {
        o0[q] = make_ulonglong2(r2a[2*q], r2a[2*q+1]);
        o1[q] = make_ulonglong2(r2b[2*q], r2b[2*q+1]);
    }
}

extern "C" void kernel_launch(void* const* d_in, const int* in_sizes, int n_in,
                              void* d_out, int out_size)
{
    const float* x   = (const float*)d_in[0];
    const float* Wq  = (const float*)d_in[1];
    const float* Wk  = (const float*)d_in[2];
    const float* Wv  = (const float*)d_in[3];
    const float* Wo  = (const float*)d_in[4];
    const float* bo  = (const float*)d_in[5];
    const float* W1  = (const float*)d_in[6];
    const float* b1  = (const float*)d_in[7];
    const float* W2  = (const float*)d_in[8];
    const float* b2  = (const float*)d_in[9];
    const float* g1  = (const float*)d_in[10];
    const float* be1 = (const float*)d_in[11];
    const float* g2  = (const float*)d_in[12];
    const float* be2 = (const float*)d_in[13];
    float* out = (float*)d_out;

    cudaFuncSetAttribute(block_kernel, cudaFuncAttributeMaxDynamicSharedMemorySize, SMEM_BYTES);
    block_kernel<<<Bsz / 2, 256, SMEM_BYTES>>>(x, Wq, Wk, Wv, Wo, bo, W1, b1, W2, b2,
                                               g1, be1, g2, be2, out);
}

// round 13
// speedup vs baseline: 1.0437x; 1.0176x over previous
#include <cuda_runtime.h>

// Fused transformer block. B=2048, T=128, DM=32, H=2, DK=16.
// CTA = 256 threads, 2 batches. Attention: thread (hb,h,u) -> rows (u,127-u), head h.
// Post-attention: threads 0..127 own row r for BOTH batches (cross-batch weight reuse).
// Packed fma.rn.f32x2 throughout. grid = 1024.

typedef unsigned long long u64;

namespace {
constexpr int Bsz = 2048;
constexpr int T   = 128;
constexpr int DM  = 32;
constexpr int KVS = 36;   // K/V row stride (floats)
constexpr int AST = 66;   // attn/x2 interleaved buffer row stride (floats)

constexpr int OFF_A  = 0;       // 4096: phase A = Wq|Wk|Wv (3072), phase B = W1 (4096)
constexpr int OFF_W2 = 4096;    // 4096
constexpr int OFF_WO = 8192;    // 1024
constexpr int OFF_B  = 9216;    // 320
constexpr int OFF_KV = 9536;    // 2 batches * (K 4608 + V 4608); attnF aliases later
constexpr int SMEM_FLOATS = OFF_KV + 2 * 2 * T * KVS;   // 27968
constexpr int SMEM_BYTES  = SMEM_FLOATS * 4;            // 111872 -> 2 CTAs/SM
}

__device__ __forceinline__ void ffma2(u64& acc, u64 a, u64 b) {
    asm("fma.rn.f32x2 %0, %1, %2, %0;" : "+l"(acc) : "l"(a), "l"(b));
}
__device__ __forceinline__ void fadd2(u64& a, u64 b) {
    asm("add.rn.f32x2 %0, %0, %1;" : "+l"(a) : "l"(b));
}
__device__ __forceinline__ u64 bcast2(float x) {
    u64 r; unsigned xi = __float_as_uint(x);
    asm("mov.b64 %0, {%1, %1};" : "=l"(r) : "r"(xi));
    return r;
}
__device__ __forceinline__ u64 pk2(float lo, float hi) {
    u64 r; unsigned a = __float_as_uint(lo), b = __float_as_uint(hi);
    asm("mov.b64 %0, {%1, %2};" : "=l"(r) : "r"(a), "r"(b));
    return r;
}
__device__ __forceinline__ float2 unpk(u64 v) {
    unsigned lo, hi;
    asm("mov.b64 {%0, %1}, %2;" : "=r"(lo), "=r"(hi) : "l"(v));
    return make_float2(__uint_as_float(lo), __uint_as_float(hi));
}
__device__ __forceinline__ void split_bcast(u64 v, u64& m0, u64& m1) {
    unsigned lo, hi;
    asm("mov.b64 {%0, %1}, %2;" : "=r"(lo), "=r"(hi) : "l"(v));
    asm("mov.b64 %0, {%1, %1};" : "=l"(m0) : "r"(lo));
    asm("mov.b64 %0, {%1, %1};" : "=l"(m1) : "r"(hi));
}

__device__ __forceinline__ void ln_row(float* x, const float* g, const float* be) {
    float mu = 0.f;
    #pragma unroll
    for (int d = 0; d < DM; d++) mu += x[d];
    mu *= (1.f / DM);
    float var = 0.f;
    #pragma unroll
    for (int d = 0; d < DM; d++) { float c = x[d] - mu; var = fmaf(c, c, var); }
    var *= (1.f / DM);
    float r = rsqrtf(var + 1e-5f);
    #pragma unroll
    for (int d = 0; d < DM; d++) x[d] = (x[d] - mu) * r * g[d] + be[d];
}

__device__ __forceinline__ void proj_h(const float* __restrict__ W,
                                       const float* __restrict__ xa,
                                       const float* __restrict__ xb,
                                       u64* oa, u64* ob) {
    #pragma unroll 8
    for (int d = 0; d < 32; d++) {
        u64 ma = bcast2(xa[d]), mb = bcast2(xb[d]);
        const ulonglong2* wp = (const ulonglong2*)(W + d * 16);
        #pragma unroll
        for (int t = 0; t < 4; t++) {
            ulonglong2 wv = wp[t];
            ffma2(oa[2*t],   ma, wv.x); ffma2(oa[2*t+1],   ma, wv.y);
            ffma2(ob[2*t],   mb, wv.x); ffma2(ob[2*t+1],   mb, wv.y);
        }
    }
}

// 16-dim dot: packed accumulate, single pair-add reduce, one unpack
__device__ __forceinline__ float dot8r(const u64* q2, const ulonglong2* kv) {
    u64 s0 = 0, s1 = 0;
    #pragma unroll
    for (int t = 0; t < 4; t++) { ffma2(s0, q2[2*t], kv[t].x); ffma2(s1, q2[2*t+1], kv[t].y); }
    fadd2(s0, s1);
    float2 a = unpk(s0);
    return a.x + a.y;
}

__global__ void __launch_bounds__(256, 2) block_kernel(
    const float* __restrict__ gx,
    const float* __restrict__ gWq, const float* __restrict__ gWk, const float* __restrict__ gWv,
    const float* __restrict__ gWo, const float* __restrict__ gbo,
    const float* __restrict__ gW1, const float* __restrict__ gb1,
    const float* __restrict__ gW2, const float* __restrict__ gb2,
    const float* __restrict__ gg1, const float* __restrict__ gbe1,
    const float* __restrict__ gg2, const float* __restrict__ gbe2,
    float* __restrict__ gout)
{
    extern __shared__ float sm[];
    float* sA    = sm + OFF_A;
    float* sW2   = sm + OFF_W2;
    float* sWo   = sm + OFF_WO;
    float* sbo   = sm + OFF_B;
    float* sb1   = sm + OFF_B + 32;
    float* sb2   = sm + OFF_B + 160;
    float* sg1   = sm + OFF_B + 192;
    float* sbe1  = sm + OFF_B + 224;
    float* sg2   = sm + OFF_B + 256;
    float* sbe2  = sm + OFF_B + 288;
    float* attnF = sm + OFF_KV;

    const int tid = threadIdx.x;
    const int hb  = tid >> 7;
    const int t7  = tid & 127;
    const int h   = t7 >> 6;
    const int u   = t7 & 63;
    const int ra  = u;
    const int rb  = 127 - u;
    const long gb = (long)blockIdx.x * 2 + hb;

    float* sK = sm + OFF_KV + hb * (2 * T * KVS);
    float* sV = sK + T * KVS;

    // ---- phase A: cooperative weight loads ----
    {
        float4*       dq = (float4*)sA;
        const float4* s;
        s = (const float4*)gWq; for (int i = tid; i < 256;  i += 256) dq[i]       = s[i];
        s = (const float4*)gWk; for (int i = tid; i < 256;  i += 256) dq[256 + i] = s[i];
        s = (const float4*)gWv; for (int i = tid; i < 256;  i += 256) dq[512 + i] = s[i];
        float4* d2 = (float4*)sW2; s = (const float4*)gW2; for (int i = tid; i < 1024; i += 256) d2[i] = s[i];
        float4* d3 = (float4*)sWo; s = (const float4*)gWo; for (int i = tid; i < 256;  i += 256) d3[i] = s[i];
        if (tid < 32) {
            sbo[tid]  = gbo[tid];  sb2[tid]  = gb2[tid];
            sg1[tid]  = gg1[tid];  sbe1[tid] = gbe1[tid];
            sg2[tid]  = gg2[tid];  sbe2[tid] = gbe2[tid];
        }
        if (tid < 128) sb1[tid] = gb1[tid];
    }
    __syncthreads();

    // ---- x rows + LN1 ----
    float xa[DM], xb[DM];
    {
        const float4* pa = (const float4*)(gx + (gb * T + ra) * DM);
        const float4* pb = (const float4*)(gx + (gb * T + rb) * DM);
        #pragma unroll
        for (int i = 0; i < 8; i++) {
            float4 v = pa[i]; xa[4*i] = v.x; xa[4*i+1] = v.y; xa[4*i+2] = v.z; xa[4*i+3] = v.w;
            float4 w = pb[i]; xb[4*i] = w.x; xb[4*i+1] = w.y; xb[4*i+2] = w.z; xb[4*i+3] = w.w;
        }
        ln_row(xa, sg1, sbe1);
        ln_row(xb, sg1, sbe1);
    }

    // ---- head-h projections: k, v to smem; q kept live ----
    {
        u64 k2a[8], k2b[8];
        #pragma unroll
        for (int p = 0; p < 8; p++) { k2a[p] = 0; k2b[p] = 0; }
        proj_h(sA + 1024 + h * 512, xa, xb, k2a, k2b);
        u64* krA = (u64*)(sK + ra * KVS + h * 16);
        u64* krB = (u64*)(sK + rb * KVS + h * 16);
        #pragma unroll
        for (int p = 0; p < 8; p++) { krA[p] = k2a[p]; krB[p] = k2b[p]; }
    }
    {
        u64 v2a[8], v2b[8];
        #pragma unroll
        for (int p = 0; p < 8; p++) { v2a[p] = 0; v2b[p] = 0; }
        proj_h(sA + 2048 + h * 512, xa, xb, v2a, v2b);
        u64* vrA = (u64*)(sV + ra * KVS + h * 16);
        u64* vrB = (u64*)(sV + rb * KVS + h * 16);
        #pragma unroll
        for (int p = 0; p < 8; p++) { vrA[p] = v2a[p]; vrB[p] = v2b[p]; }
    }
    u64 qa2[8], qb2[8];
    #pragma unroll
    for (int p = 0; p < 8; p++) { qa2[p] = 0; qb2[p] = 0; }
    proj_h(sA + h * 512, xa, xb, qa2, qb2);

    __syncthreads();   // K/V visible; QKV weights dead

    // stage W1 into region A (overlaps attention)
    {
        const float4* s = (const float4*)gW1;
        float4*       d = (float4*)sA;
        #pragma unroll
        for (int i = tid; i < 1024; i += 256) d[i] = s[i];
    }

    // ---- attention: rows (u,127-u), head h; two warp-uniform segments ----
    u64 aa2[8], ab2[8];
    #pragma unroll
    for (int p = 0; p < 8; p++) { aa2[p] = 0; ab2[p] = 0; }
    float la = 0.f, lb = 0.f;

    const int ub     = u & 32;
    const int wa_max = ub + 31;
    const int wb_max = 127 - ub;
    const float* kh = sK + h * 16;
    const float* vh = sV + h * 16;

    for (int s = 0; s <= wa_max; s++) {
        const ulonglong2* kp = (const ulonglong2*)(kh + s * KVS);
        ulonglong2 kv[4];
        #pragma unroll
        for (int q = 0; q < 4; q++) kv[q] = kp[q];
        float da = dot8r(qa2, kv);
        float db = dot8r(qb2, kv);
        float pa = (s <= ra) ? __expf(da) : 0.f;
        float pb = __expf(db);
        la += pa; lb += pb;

        const ulonglong2* vp = (const ulonglong2*)(vh + s * KVS);
        ulonglong2 vv[4];
        #pragma unroll
        for (int q = 0; q < 4; q++) vv[q] = vp[q];
        u64 Pa = bcast2(pa), Pb = bcast2(pb);
        #pragma unroll
        for (int q = 0; q < 4; q++) {
            ffma2(aa2[2*q],   Pa, vv[q].x); ffma2(aa2[2*q+1],   Pa, vv[q].y);
            ffma2(ab2[2*q],   Pb, vv[q].x); ffma2(ab2[2*q+1],   Pb, vv[q].y);
        }
    }
    for (int s = wa_max + 1; s <= wb_max; s++) {
        const ulonglong2* kp = (const ulonglong2*)(kh + s * KVS);
        ulonglong2 kv[4];
        #pragma unroll
        for (int q = 0; q < 4; q++) kv[q] = kp[q];
        float db = dot8r(qb2, kv);
        float pb = (s <= rb) ? __expf(db) : 0.f;
        lb += pb;

        const ulonglong2* vp = (const ulonglong2*)(vh + s * KVS);
        u64 Pb = bcast2(pb);
        #pragma unroll
        for (int q = 0; q < 4; q++) {
            ulonglong2 vv = vp[q];
            ffma2(ab2[2*q], Pb, vv.x); ffma2(ab2[2*q+1], Pb, vv.y);
        }
    }

    __syncthreads();   // all K/V reads done; region becomes interleaved attn buffer

    // ---- store normalized attn, batch-interleaved: attnF[r*AST + 2*j + hb] ----
    {
        float ia = 1.f / la, ib = 1.f / lb;
        float* pA = attnF + ra * AST + hb;
        float* pB = attnF + rb * AST + hb;
        #pragma unroll
        for (int p = 0; p < 8; p++) {
            int j0 = 16 * h + 2 * p;
            float2 f = unpk(aa2[p]);
            pA[2*j0]       = f.x * ia;
            pA[2*(j0+1)]   = f.y * ia;
            float2 g = unpk(ab2[p]);
            pB[2*j0]       = g.x * ib;
            pB[2*(j0+1)]   = g.y * ib;
        }
    }
    __syncthreads();

    // ==== post-attention: threads 0..127, row t for BOTH batches ====
    if (tid >= 128) return;
    const int t = tid;
    const long gB0 = (long)blockIdx.x * 2;
    const long gB1 = gB0 + 1;

    // Wo accumulators initialized with residual LN1(x) + bo
    u64 oA[16], oB[16];
    {
        float xA[DM], xB[DM];
        const float4* p0 = (const float4*)(gx + (gB0 * T + t) * DM);
        const float4* p1 = (const float4*)(gx + (gB1 * T + t) * DM);
        #pragma unroll
        for (int i = 0; i < 8; i++) {
            float4 v = p0[i]; xA[4*i] = v.x; xA[4*i+1] = v.y; xA[4*i+2] = v.z; xA[4*i+3] = v.w;
            float4 w = p1[i]; xB[4*i] = w.x; xB[4*i+1] = w.y; xB[4*i+2] = w.z; xB[4*i+3] = w.w;
        }
        ln_row(xA, sg1, sbe1);
        ln_row(xB, sg1, sbe1);
        #pragma unroll
        for (int p = 0; p < 16; p++) {
            oA[p] = pk2(xA[2*p] + sbo[2*p], xA[2*p+1] + sbo[2*p+1]);
            oB[p] = pk2(xB[2*p] + sbo[2*p], xB[2*p+1] + sbo[2*p+1]);
        }
    }

    // attn @ Wo, both batches share each Wo load
    const float* myrow = attnF + t * AST;
    #pragma unroll 4
    for (int e = 0; e < 32; e++) {
        u64 ap = *(const u64*)(myrow + 2 * e);
        u64 m0, m1; split_bcast(ap, m0, m1);
        const ulonglong2* wp = (const ulonglong2*)(sWo + e * 32);
        #pragma unroll
        for (int q = 0; q < 8; q++) {
            ulonglong2 wv = wp[q];
            ffma2(oA[2*q], m0, wv.x); ffma2(oA[2*q+1], m0, wv.y);
            ffma2(oB[2*q], m1, wv.x); ffma2(oB[2*q+1], m1, wv.y);
        }
    }

    // LN2, stash x2 pairs in smem (same row, in place), init FFN residual accumulators
    u64 r2a[16], r2b[16];
    {
        float x2A[DM], x2B[DM];
        #pragma unroll
        for (int p = 0; p < 16; p++) {
            float2 f = unpk(oA[p]); x2A[2*p] = f.x; x2A[2*p+1] = f.y;
            float2 g = unpk(oB[p]); x2B[2*p] = g.x; x2B[2*p+1] = g.y;
        }
        ln_row(x2A, sg2, sbe2);
        ln_row(x2B, sg2, sbe2);
        u64* xrow = (u64*)myrow;
        #pragma unroll
        for (int d = 0; d < 32; d++) xrow[d] = pk2(x2A[d], x2B[d]);
        #pragma unroll
        for (int p = 0; p < 16; p++) {
            r2a[p] = pk2(x2A[2*p] + sb2[2*p], x2A[2*p+1] + sb2[2*p+1]);
            r2b[p] = pk2(x2B[2*p] + sb2[2*p], x2B[2*p+1] + sb2[2*p+1]);
        }
    }

    // ---- FFN: hidden in blocks of 16; x2 pairs re-read from smem; weights shared 2 rows ----
    #pragma unroll 1
    for (int blk = 0; blk < 8; blk++) {
        const float* w1p = sA + blk * 16;
        u64 h0[8], h1[8];
        #pragma unroll
        for (int p = 0; p < 8; p++) { h0[p] = 0; h1[p] = 0; }
        #pragma unroll 4
        for (int d = 0; d < 32; d++) {
            u64 xp = *(const u64*)(myrow + 2 * d);
            u64 m0, m1; split_bcast(xp, m0, m1);
            const ulonglong2* wp = (const ulonglong2*)(w1p + d * 128);
            #pragma unroll
            for (int q = 0; q < 4; q++) {
                ulonglong2 wv = wp[q];
                ffma2(h0[2*q],   m0, wv.x); ffma2(h0[2*q+1],   m0, wv.y);
                ffma2(h1[2*q],   m1, wv.x); ffma2(h1[2*q+1],   m1, wv.y);
            }
        }
        #pragma unroll
        for (int p = 0; p < 8; p++) {
            const int j = blk * 16 + 2 * p;
            float2 f0 = unpk(h0[p]);
            float2 f1 = unpk(h1[p]);
            float A0 = fmaxf(f0.x + sb1[j],     0.f);
            float A1 = fmaxf(f0.y + sb1[j + 1], 0.f);
            float B0 = fmaxf(f1.x + sb1[j],     0.f);
            float B1 = fmaxf(f1.y + sb1[j + 1], 0.f);
            {
                u64 Pa = bcast2(A0), Pb = bcast2(B0);
                const ulonglong2* w2 = (const ulonglong2*)(sW2 + j * 32);
                #pragma unroll
                for (int q = 0; q < 8; q++) {
                    ulonglong2 wv = w2[q];
                    ffma2(r2a[2*q], Pa, wv.x); ffma2(r2a[2*q+1], Pa, wv.y);
                    ffma2(r2b[2*q], Pb, wv.x); ffma2(r2b[2*q+1], Pb, wv.y);
                }
            }
            {
                u64 Pa = bcast2(A1), Pb = bcast2(B1);
                const ulonglong2* w2 = (const ulonglong2*)(sW2 + (j + 1) * 32);
                #pragma unroll
                for (int q = 0; q < 8; q++) {
                    ulonglong2 wv = w2[q];
                    ffma2(r2a[2*q], Pa, wv.x); ffma2(r2a[2*q+1], Pa, wv.y);
                    ffma2(r2b[2*q], Pb, wv.x); ffma2(r2b[2*q+1], Pb, wv.y);
                }
            }
        }
    }

    // ---- store both batches' row t ----
    ulonglong2* o0 = (ulonglong2*)(gout + (gB0 * T + t) * DM);
    ulonglong2* o1 = (ulonglong2*)(gout + (gB1 * T + t) * DM);
    #pragma unroll
    for (int q = 0; q < 8; q++) {
        o0[q] = make_ulonglong2(r2a[2*q], r2a[2*q+1]);
        o1[q] = make_ulonglong2(r2b[2*q], r2b[2*q+1]);
    }
}

extern "C" void kernel_launch(void* const* d_in, const int* in_sizes, int n_in,
                              void* d_out, int out_size)
{
    const float* x   = (const float*)d_in[0];
    const float* Wq  = (const float*)d_in[1];
    const float* Wk  = (const float*)d_in[2];
    const float* Wv  = (const float*)d_in[3];
    const float* Wo  = (const float*)d_in[4];
    const float* bo  = (const float*)d_in[5];
    const float* W1  = (const float*)d_in[6];
    const float* b1  = (const float*)d_in[7];
    const float* W2  = (const float*)d_in[8];
    const float* b2  = (const float*)d_in[9];
    const float* g1  = (const float*)d_in[10];
    const float* be1 = (const float*)d_in[11];
    const float* g2  = (const float*)d_in[12];
    const float* be2 = (const float*)d_in[13];
    float* out = (float*)d_out;

    cudaFuncSetAttribute(block_kernel, cudaFuncAttributeMaxDynamicSharedMemorySize, SMEM_BYTES);
    block_kernel<<<Bsz / 2, 256, SMEM_BYTES>>>(x, Wq, Wk, Wv, Wo, bo, W1, b1, W2, b2,
                                               g1, be1, g2, be2, out);
}